// round 2
// baseline (speedup 1.0000x reference)
#include <cuda_runtime.h>

#define TILE    128
#define THREADS 512
#define INF     97     // input features
#define INP     98     // padded input stride (floats)
#define MID     80
#define OUTD    64
#define HSTRIDE 82     // padded H stride (41 doubles)
#define OSTRIDE 65     // padded output staging stride (odd -> conflict-free)

// packed dual-fp32 FMA (sm_100+): 2x throughput vs 3-reg FFMA on sm_103a
__device__ __forceinline__ float2 ffma2(float2 a, float2 b, float2 c) {
    unsigned long long au = *reinterpret_cast<unsigned long long*>(&a);
    unsigned long long bu = *reinterpret_cast<unsigned long long*>(&b);
    unsigned long long cu = *reinterpret_cast<unsigned long long*>(&c);
    asm("fma.rn.f32x2 %0, %1, %2, %0;" : "+l"(cu) : "l"(au), "l"(bu));
    return *reinterpret_cast<float2*>(&cu);
}

// tanh via 2 MUFU ops (EX2 + RCP), ~2^-20 rel error, saturates correctly
__device__ __forceinline__ float fast_tanh(float x) {
    float e = __expf(2.0f * x);
    return 1.0f - __fdividef(2.0f, e + 1.0f);
}

extern __shared__ float smem[];

__global__ void __launch_bounds__(THREADS, 1)
edge_mlp_kernel(const float* __restrict__ dstf, const float* __restrict__ dsth,
                const float* __restrict__ srcf, const float* __restrict__ srch,
                const float* __restrict__ ef,
                const float* __restrict__ W1, const float* __restrict__ b1,
                const float* __restrict__ W2, const float* __restrict__ b2,
                float* __restrict__ out, int E)
{
    float* Xs  = smem;                    // TILE*INP floats (reused as output stage)
    float* Hs  = Xs  + TILE * INP;        // TILE*HSTRIDE
    float* W1s = Hs  + TILE * HSTRIDE;    // MID*INP
    float* W2s = W1s + MID * INP;         // OUTD*MID
    float* b1s = W2s + OUTD * MID;        // MID
    float* b2s = b1s + MID;               // OUTD

    const int tid  = threadIdx.x;
    const int lane = tid & 31;
    const int warp = tid >> 5;            // 0..15

    // ---- stage weights once per (persistent) block ----
    for (int i = tid; i < MID * INF; i += THREADS) {
        int m = i / INF, k = i - m * INF;
        W1s[m * INP + k] = W1[i];
    }
    for (int m = tid; m < MID; m += THREADS) W1s[m * INP + INF] = 0.0f; // zero pad col
    for (int i = tid; i < OUTD * MID; i += THREADS) W2s[i] = W2[i];
    for (int i = tid; i < MID;  i += THREADS) b1s[i] = b1[i];
    for (int i = tid; i < OUTD; i += THREADS) b2s[i] = b2[i];
    __syncthreads();

    const int ntiles = (E + TILE - 1) / TILE;

    for (int tile = blockIdx.x; tile < ntiles; tile += gridDim.x) {
        const int e0  = tile * TILE;
        int rem = E - e0; if (rem > TILE) rem = TILE;

        // ---- stage X tile: [dstf(16) | dsth(32) | srcf(16) | srch(32) | edge | 0] ----
        {
            const float2* s0 = (const float2*)(dstf + (size_t)e0 * 16);
            const float2* s1 = (const float2*)(dsth + (size_t)e0 * 32);
            const float2* s2 = (const float2*)(srcf + (size_t)e0 * 16);
            const float2* s3 = (const float2*)(srch + (size_t)e0 * 32);
            float2* X2 = (float2*)Xs;  // row stride 49 double-units
            for (int i = tid; i < TILE * 8; i += THREADS) {
                int r = i >> 3, c = i & 7;
                if (r < rem) X2[r * 49 + c] = s0[r * 8 + c];
            }
            for (int i = tid; i < TILE * 16; i += THREADS) {
                int r = i >> 4, c = i & 15;
                if (r < rem) X2[r * 49 + 8 + c] = s1[r * 16 + c];
            }
            for (int i = tid; i < TILE * 8; i += THREADS) {
                int r = i >> 3, c = i & 7;
                if (r < rem) X2[r * 49 + 24 + c] = s2[r * 8 + c];
            }
            for (int i = tid; i < TILE * 16; i += THREADS) {
                int r = i >> 4, c = i & 15;
                if (r < rem) X2[r * 49 + 32 + c] = s3[r * 16 + c];
            }
            for (int r = tid; r < TILE; r += THREADS) {
                Xs[r * INP + 96] = (r < rem) ? ef[e0 + r] : 0.0f;
                Xs[r * INP + 97] = 0.0f;
            }
        }
        __syncthreads();

        // ---- phase A: H = relu(X @ W1^T + b1); warp -> 5 m-outputs x 128 edges ----
        {
            const float2* X2  = (const float2*)Xs;
            const float2* W12 = (const float2*)W1s;  // row stride 49 double-units
            const int m0 = warp * 5;
            float2 acc[4][5];
            #pragma unroll
            for (int r = 0; r < 4; r++)
                #pragma unroll
                for (int j = 0; j < 5; j++) acc[r][j] = make_float2(0.f, 0.f);

            for (int kk = 0; kk < 49; ++kk) {
                float2 x0 = X2[(lane      ) * 49 + kk];
                float2 x1 = X2[(lane +  32) * 49 + kk];
                float2 x2 = X2[(lane +  64) * 49 + kk];
                float2 x3 = X2[(lane +  96) * 49 + kk];
                #pragma unroll
                for (int j = 0; j < 5; j++) {
                    float2 w = W12[(m0 + j) * 49 + kk];   // warp-uniform broadcast
                    acc[0][j] = ffma2(x0, w, acc[0][j]);
                    acc[1][j] = ffma2(x1, w, acc[1][j]);
                    acc[2][j] = ffma2(x2, w, acc[2][j]);
                    acc[3][j] = ffma2(x3, w, acc[3][j]);
                }
            }
            #pragma unroll
            for (int j = 0; j < 5; j++) {
                float bb = b1s[m0 + j];
                #pragma unroll
                for (int r = 0; r < 4; r++) {
                    float s = acc[r][j].x + acc[r][j].y + bb;
                    Hs[(lane + r * 32) * HSTRIDE + m0 + j] = fmaxf(s, 0.0f);
                }
            }
        }
        __syncthreads();

        // ---- phase B: O = tanh(H @ W2^T + b2); warp -> 4 o-outputs x 128 edges ----
        {
            const float2* H2  = (const float2*)Hs;   // row stride 41
            const float2* W22 = (const float2*)W2s;  // row stride 40
            float* Ot = Xs;                          // reuse X buffer as staging
            const int o0 = warp * 4;
            float2 acc[4][4];
            #pragma unroll
            for (int r = 0; r < 4; r++)
                #pragma unroll
                for (int j = 0; j < 4; j++) acc[r][j] = make_float2(0.f, 0.f);

            for (int kk = 0; kk < 40; ++kk) {
                float2 h0 = H2[(lane      ) * 41 + kk];
                float2 h1 = H2[(lane +  32) * 41 + kk];
                float2 h2 = H2[(lane +  64) * 41 + kk];
                float2 h3 = H2[(lane +  96) * 41 + kk];
                #pragma unroll
                for (int j = 0; j < 4; j++) {
                    float2 w = W22[(o0 + j) * 40 + kk];   // warp-uniform broadcast
                    acc[0][j] = ffma2(h0, w, acc[0][j]);
                    acc[1][j] = ffma2(h1, w, acc[1][j]);
                    acc[2][j] = ffma2(h2, w, acc[2][j]);
                    acc[3][j] = ffma2(h3, w, acc[3][j]);
                }
            }
            #pragma unroll
            for (int j = 0; j < 4; j++) {
                float bb = b2s[o0 + j];
                #pragma unroll
                for (int r = 0; r < 4; r++) {
                    float s = acc[r][j].x + acc[r][j].y + bb;
                    Ot[(lane + r * 32) * OSTRIDE + o0 + j] = fast_tanh(s);
                }
            }
        }
        __syncthreads();

        // ---- coalesced write-out ----
        {
            float* outp = out + (size_t)e0 * OUTD;
            for (int i = tid; i < TILE * OUTD; i += THREADS) {
                int r = i >> 6, c = i & 63;
                if (r < rem) outp[i] = Xs[r * OSTRIDE + c];
            }
        }
        __syncthreads();  // protect Xs before next tile's staging
    }
}

extern "C" void kernel_launch(void* const* d_in, const int* in_sizes, int n_in,
                              void* d_out, int out_size) {
    const float* dstf = (const float*)d_in[0];
    const float* dsth = (const float*)d_in[1];
    const float* srcf = (const float*)d_in[2];
    const float* srch = (const float*)d_in[3];
    const float* ef   = (const float*)d_in[4];
    const float* W1   = (const float*)d_in[5];
    const float* b1   = (const float*)d_in[6];
    const float* W2   = (const float*)d_in[7];
    const float* b2   = (const float*)d_in[8];
    float* out = (float*)d_out;
    const int E = in_sizes[4];
    (void)n_in; (void)out_size;

    const int smem_bytes = (TILE * INP + TILE * HSTRIDE + MID * INP +
                            OUTD * MID + MID + OUTD) * (int)sizeof(float);  // 144,576 B

    cudaFuncSetAttribute(edge_mlp_kernel,
                         cudaFuncAttributeMaxDynamicSharedMemorySize, smem_bytes);

    int sms = 148;
    cudaDeviceGetAttribute(&sms, cudaDevAttrMultiProcessorCount, 0);

    edge_mlp_kernel<<<sms, THREADS, smem_bytes>>>(
        dstf, dsth, srcf, srch, ef, W1, b1, W2, b2, out, E);
}

// round 4
// speedup vs baseline: 1.2470x; 1.2470x over previous
#include <cuda_runtime.h>

#define TILE    128
#define THREADS 1024
#define INF     97      // real input features
#define INP     100     // padded X/W1 row stride (floats); stride%8==4 -> LDS.128 conflict-free
#define INP4    25
#define MID     80
#define OUTD    64
#define HSTR    84      // H row stride; 84/4=21 odd -> LDS.128 conflict-free
#define HSTR4   21
#define W2STR   80
#define W2STR4  20
#define OSTR    68      // output staging stride; 68/4=17 odd -> conflict-free float4 reads
#define OSTR4   17

__device__ __forceinline__ float2 ffma2(float2 a, float2 b, float2 c) {
    unsigned long long au = *reinterpret_cast<unsigned long long*>(&a);
    unsigned long long bu = *reinterpret_cast<unsigned long long*>(&b);
    unsigned long long cu = *reinterpret_cast<unsigned long long*>(&c);
    asm("fma.rn.f32x2 %0, %1, %2, %0;" : "+l"(cu) : "l"(au), "l"(bu));
    return *reinterpret_cast<float2*>(&cu);
}

__device__ __forceinline__ float fast_tanh(float x) {
    float e = __expf(2.0f * x);
    return 1.0f - __fdividef(2.0f, e + 1.0f);
}

extern __shared__ float smem[];

__global__ void __launch_bounds__(THREADS, 1)
edge_mlp_kernel(const float* __restrict__ dstf, const float* __restrict__ dsth,
                const float* __restrict__ srcf, const float* __restrict__ srch,
                const float* __restrict__ ef,
                const float* __restrict__ W1, const float* __restrict__ b1,
                const float* __restrict__ W2, const float* __restrict__ b2,
                float* __restrict__ out, int E)
{
    float* Xs  = smem;                    // TILE*INP (reused as output staging, stride OSTR)
    float* Hs  = Xs  + TILE * INP;        // TILE*HSTR
    float* W1s = Hs  + TILE * HSTR;       // MID*INP
    float* W2s = W1s + MID * INP;         // OUTD*W2STR
    float* b1s = W2s + OUTD * W2STR;      // MID
    float* b2s = b1s + MID;               // OUTD

    const int tid  = threadIdx.x;
    const int lane = tid & 31;
    const int warp = tid >> 5;            // 0..31
    const int mg   = warp & 15;           // m/o group
    const int eb   = (warp >> 4) * 64;    // edge half base
    const int r0   = eb + lane;
    const int r1   = eb + lane + 32;

    // ---- stage weights once per (persistent) block ----
    for (int i = tid; i < MID * INF; i += THREADS) {
        int m = i / INF, k = i - m * INF;
        W1s[m * INP + k] = W1[i];
    }
    for (int i = tid; i < MID * 3; i += THREADS)      // zero pad cols 97..99
        W1s[(i / 3) * INP + 97 + (i % 3)] = 0.0f;
    for (int i = tid; i < OUTD * MID; i += THREADS) W2s[i] = W2[i];
    for (int i = tid; i < MID;  i += THREADS) b1s[i] = b1[i];
    for (int i = tid; i < OUTD; i += THREADS) b2s[i] = b2[i];
    __syncthreads();

    const int ntiles = (E + TILE - 1) / TILE;

    for (int tile = blockIdx.x; tile < ntiles; tile += gridDim.x) {
        const int e0  = tile * TILE;
        int rem = E - e0; if (rem > TILE) rem = TILE;

        // ---- stage X tile (float4 idx): dstf->0..3 | dsth->4..11 | srcf->12..15 |
        //                                 srch->16..23 | {ef,0,0,0}->24 ----
        {
            const float4* s0 = (const float4*)(dstf + (size_t)e0 * 16);
            const float4* s1 = (const float4*)(dsth + (size_t)e0 * 32);
            const float4* s2 = (const float4*)(srcf + (size_t)e0 * 16);
            const float4* s3 = (const float4*)(srch + (size_t)e0 * 32);
            float4* X4 = (float4*)Xs;  // row stride INP4=25
            for (int i = tid; i < TILE * 4; i += THREADS) {
                int r = i >> 2, c = i & 3;
                if (r < rem) X4[r * INP4 + c] = s0[r * 4 + c];
            }
            for (int i = tid; i < TILE * 8; i += THREADS) {
                int r = i >> 3, c = i & 7;
                if (r < rem) X4[r * INP4 + 4 + c] = s1[r * 8 + c];
            }
            for (int i = tid; i < TILE * 4; i += THREADS) {
                int r = i >> 2, c = i & 3;
                if (r < rem) X4[r * INP4 + 12 + c] = s2[r * 4 + c];
            }
            for (int i = tid; i < TILE * 8; i += THREADS) {
                int r = i >> 3, c = i & 7;
                if (r < rem) X4[r * INP4 + 16 + c] = s3[r * 8 + c];
            }
            for (int r = tid; r < TILE; r += THREADS)
                X4[r * INP4 + 24] = make_float4(r < rem ? ef[e0 + r] : 0.0f, 0.f, 0.f, 0.f);
        }
        __syncthreads();

        // ---- phase A: H = relu(X @ W1^T + b1); warp -> 5 m x 64 edges (2 rows/lane) ----
        {
            const float4* X4  = (const float4*)Xs;
            const float4* W14 = (const float4*)W1s;
            const int m0 = mg * 5;
            float2 acc[2][5];
            #pragma unroll
            for (int r = 0; r < 2; r++)
                #pragma unroll
                for (int j = 0; j < 5; j++) acc[r][j] = make_float2(0.f, 0.f);

            #pragma unroll
            for (int it = 0; it < INP4; ++it) {
                float4 x0 = X4[r0 * INP4 + it];
                float4 x1 = X4[r1 * INP4 + it];
                #pragma unroll
                for (int j = 0; j < 5; j++) {
                    float4 w = W14[(m0 + j) * INP4 + it];   // warp-uniform broadcast
                    acc[0][j] = ffma2(make_float2(x0.x, x0.y), make_float2(w.x, w.y), acc[0][j]);
                    acc[0][j] = ffma2(make_float2(x0.z, x0.w), make_float2(w.z, w.w), acc[0][j]);
                    acc[1][j] = ffma2(make_float2(x1.x, x1.y), make_float2(w.x, w.y), acc[1][j]);
                    acc[1][j] = ffma2(make_float2(x1.z, x1.w), make_float2(w.z, w.w), acc[1][j]);
                }
            }
            #pragma unroll
            for (int j = 0; j < 5; j++) {
                float bb = b1s[m0 + j];
                float sa = acc[0][j].x + acc[0][j].y + bb;
                float sb = acc[1][j].x + acc[1][j].y + bb;
                Hs[r0 * HSTR + m0 + j] = fmaxf(sa, 0.0f);
                Hs[r1 * HSTR + m0 + j] = fmaxf(sb, 0.0f);
            }
        }
        __syncthreads();

        // ---- phase B: O = tanh(H @ W2^T + b2); warp -> 4 o x 64 edges ----
        {
            const float4* H4  = (const float4*)Hs;
            const float4* W24 = (const float4*)W2s;
            float* Ot = Xs;                          // reuse X buffer, stride OSTR
            const int o0 = mg * 4;
            float2 acc[2][4];
            #pragma unroll
            for (int r = 0; r < 2; r++)
                #pragma unroll
                for (int j = 0; j < 4; j++) acc[r][j] = make_float2(0.f, 0.f);

            #pragma unroll
            for (int it = 0; it < W2STR4; ++it) {
                float4 h0 = H4[r0 * HSTR4 + it];
                float4 h1 = H4[r1 * HSTR4 + it];
                #pragma unroll
                for (int j = 0; j < 4; j++) {
                    float4 w = W24[(o0 + j) * W2STR4 + it];  // warp-uniform broadcast
                    acc[0][j] = ffma2(make_float2(h0.x, h0.y), make_float2(w.x, w.y), acc[0][j]);
                    acc[0][j] = ffma2(make_float2(h0.z, h0.w), make_float2(w.z, w.w), acc[0][j]);
                    acc[1][j] = ffma2(make_float2(h1.x, h1.y), make_float2(w.x, w.y), acc[1][j]);
                    acc[1][j] = ffma2(make_float2(h1.z, h1.w), make_float2(w.z, w.w), acc[1][j]);
                }
            }
            #pragma unroll
            for (int j = 0; j < 4; j++) {
                float bb = b2s[o0 + j];
                float sa = acc[0][j].x + acc[0][j].y + bb;
                float sb = acc[1][j].x + acc[1][j].y + bb;
                Ot[r0 * OSTR + o0 + j] = fast_tanh(sa);
                Ot[r1 * OSTR + o0 + j] = fast_tanh(sb);
            }
        }
        __syncthreads();

        // ---- coalesced float4 write-out ----
        {
            const float4* O4 = (const float4*)Xs;    // stride OSTR4=17
            float4* outp = (float4*)(out + (size_t)e0 * OUTD);
            for (int i = tid; i < TILE * 16; i += THREADS) {
                int r = i >> 4, c = i & 15;
                if (r < rem) outp[r * 16 + c] = O4[r * OSTR4 + c];
            }
        }
        __syncthreads();  // protect Xs before next tile's staging
    }
}

extern "C" void kernel_launch(void* const* d_in, const int* in_sizes, int n_in,
                              void* d_out, int out_size) {
    const float* dstf = (const float*)d_in[0];
    const float* dsth = (const float*)d_in[1];
    const float* srcf = (const float*)d_in[2];
    const float* srch = (const float*)d_in[3];
    const float* ef   = (const float*)d_in[4];
    const float* W1   = (const float*)d_in[5];
    const float* b1   = (const float*)d_in[6];
    const float* W2   = (const float*)d_in[7];
    const float* b2   = (const float*)d_in[8];
    float* out = (float*)d_out;
    const int E = in_sizes[4];
    (void)n_in; (void)out_size;

    const int smem_bytes = (TILE * INP + TILE * HSTR + MID * INP +
                            OUTD * W2STR + MID + OUTD) * (int)sizeof(float);  // ~147 KB

    cudaFuncSetAttribute(edge_mlp_kernel,
                         cudaFuncAttributeMaxDynamicSharedMemorySize, smem_bytes);

    int sms = 148;
    cudaDeviceGetAttribute(&sms, cudaDevAttrMultiProcessorCount, 0);

    edge_mlp_kernel<<<sms, THREADS, smem_bytes>>>(
        dstf, dsth, srcf, srch, ef, W1, b1, W2, b2, out, E);
}